// round 1
// baseline (speedup 1.0000x reference)
#include <cuda_runtime.h>
#include <math.h>

#define B_   32
#define SX_  2048
#define SY_  2048
#define DD   160

// Scratch for projected Q, K, V (static device globals: allowed, no runtime alloc)
__device__ float g_q[(size_t)B_ * SX_ * DD];
__device__ float g_k[(size_t)B_ * SY_ * DD];
__device__ float g_v[(size_t)B_ * SY_ * DD];

// ---------------------------------------------------------------------------
// Projection: out[m, n] = sum_d A[m, d] * W[n, d] + bias[n]
// (torch Linear: W is [out, in], NT gemm, both operands K-contiguous)
// BM=64, BN=160(all), BK=32, 256 threads, each thread 8 rows x 5 cols
// ---------------------------------------------------------------------------
__global__ __launch_bounds__(256) void proj_kernel(
    const float* __restrict__ A, const float* __restrict__ W,
    const float* __restrict__ bias, float* __restrict__ out)
{
    __shared__ float As[64][33];    // pad 33: conflict-free column reads
    __shared__ float Ws[160][33];

    const int tid = threadIdx.x;
    const int tx  = tid & 31;       // col group: cols tx + 32u
    const int ty  = tid >> 5;       // row group: rows ty*8 + i
    const size_t m0 = (size_t)blockIdx.x * 64;

    float acc[8][5];
#pragma unroll
    for (int i = 0; i < 8; i++)
#pragma unroll
        for (int u = 0; u < 5; u++) acc[i][u] = 0.f;

    for (int k0 = 0; k0 < DD; k0 += 32) {
        // A tile 64x32: 512 float4, 2 per thread
#pragma unroll
        for (int i = 0; i < 2; i++) {
            int idx = tid + i * 256;
            int r = idx >> 3, c = (idx & 7) << 2;
            float4 t = *(const float4*)(A + (m0 + r) * DD + k0 + c);
            As[r][c] = t.x; As[r][c+1] = t.y; As[r][c+2] = t.z; As[r][c+3] = t.w;
        }
        // W tile 160x32: 1280 float4, 5 per thread
#pragma unroll
        for (int i = 0; i < 5; i++) {
            int idx = tid + i * 256;
            int r = idx >> 3, c = (idx & 7) << 2;
            float4 t = *(const float4*)(W + (size_t)r * DD + k0 + c);
            Ws[r][c] = t.x; Ws[r][c+1] = t.y; Ws[r][c+2] = t.z; Ws[r][c+3] = t.w;
        }
        __syncthreads();

#pragma unroll
        for (int d = 0; d < 32; d++) {
            float a[8], w[5];
#pragma unroll
            for (int i = 0; i < 8; i++) a[i] = As[ty * 8 + i][d];   // broadcast
#pragma unroll
            for (int u = 0; u < 5; u++) w[u] = Ws[tx + 32 * u][d];  // conflict-free
#pragma unroll
            for (int i = 0; i < 8; i++)
#pragma unroll
                for (int u = 0; u < 5; u++)
                    acc[i][u] = fmaf(a[i], w[u], acc[i][u]);
        }
        __syncthreads();
    }

#pragma unroll
    for (int u = 0; u < 5; u++) {
        float bv = bias[tx + 32 * u];
#pragma unroll
        for (int i = 0; i < 8; i++)
            out[(m0 + ty * 8 + i) * DD + tx + 32 * u] = acc[i][u] + bv;
    }
}

// ---------------------------------------------------------------------------
// Flash attention + residual.
// Block: 64 query rows of one batch. 256 threads.
//   ty = tid/16 -> rows  {ty + 16i},  i<4   (row group = 16-lane half warp)
//   tx = tid%16 -> Scols {tx + 16u},  u<4 ; Ocols {tx + 16u}, u<10
// SMEM paddings: Qs/Ks stride 161 (conflict-free strided col reads),
//                Vs stride 164 (float4 stores, conflict-free reads),
//                Ps stride 65.
// ---------------------------------------------------------------------------
#define QS_LD 161
#define KS_LD 161
#define VS_LD 164
#define PS_LD 65
#define SMEM_FLOATS (64*QS_LD + 64*KS_LD + 64*VS_LD + 64*PS_LD)

__global__ __launch_bounds__(256) void attn_kernel(
    const float* __restrict__ gq, const float* __restrict__ gk,
    const float* __restrict__ gv, const float* __restrict__ gx,
    float* __restrict__ gout)
{
    extern __shared__ float sm[];
    float* Qs = sm;                     // [64][161]
    float* Ks = Qs + 64 * QS_LD;        // [64][161]
    float* Vs = Ks + 64 * KS_LD;        // [64][164]
    float* Ps = Vs + 64 * VS_LD;        // [64][65]

    const int tid = threadIdx.x;
    const int tx  = tid & 15;
    const int ty  = tid >> 4;
    const int b   = blockIdx.y;
    const size_t m0 = (size_t)blockIdx.x * 64;

    // Load Q tile (64 x 160), coalesced float4
    const float* qbase = gq + ((size_t)b * SX_ + m0) * DD;
#pragma unroll
    for (int i = 0; i < 10; i++) {
        int idx = tid + i * 256;
        int r = idx / 40, c = (idx % 40) * 4;
        float4 t = *(const float4*)(qbase + (size_t)r * DD + c);
        float* dst = Qs + r * QS_LD + c;
        dst[0] = t.x; dst[1] = t.y; dst[2] = t.z; dst[3] = t.w;
    }

    float m_r[4], l_r[4], O[4][10];
#pragma unroll
    for (int i = 0; i < 4; i++) {
        m_r[i] = -INFINITY; l_r[i] = 0.f;
#pragma unroll
        for (int u = 0; u < 10; u++) O[i][u] = 0.f;
    }

    const float* kbase = gk + (size_t)b * SY_ * DD;
    const float* vbase = gv + (size_t)b * SY_ * DD;

    for (int j0 = 0; j0 < SY_; j0 += 64) {
        __syncthreads();   // prev-iter PV done (and Q visible on iter 0)

        // Load K, V tiles (64 x 160 each)
#pragma unroll
        for (int i = 0; i < 10; i++) {
            int idx = tid + i * 256;
            int r = idx / 40, c = (idx % 40) * 4;
            float4 tk = *(const float4*)(kbase + (size_t)(j0 + r) * DD + c);
            float* dk = Ks + r * KS_LD + c;
            dk[0] = tk.x; dk[1] = tk.y; dk[2] = tk.z; dk[3] = tk.w;
            float4 tv = *(const float4*)(vbase + (size_t)(j0 + r) * DD + c);
            *(float4*)(Vs + r * VS_LD + c) = tv;
        }
        __syncthreads();

        // S = Q K^T  (64x64 over D=160), 4x4 per thread
        float S[4][4];
#pragma unroll
        for (int i = 0; i < 4; i++)
#pragma unroll
            for (int u = 0; u < 4; u++) S[i][u] = 0.f;

#pragma unroll 8
        for (int d = 0; d < DD; d++) {
            float qv[4], kv[4];
#pragma unroll
            for (int i = 0; i < 4; i++) qv[i] = Qs[(ty + 16 * i) * QS_LD + d];
#pragma unroll
            for (int u = 0; u < 4; u++) kv[u] = Ks[(tx + 16 * u) * KS_LD + d];
#pragma unroll
            for (int i = 0; i < 4; i++)
#pragma unroll
                for (int u = 0; u < 4; u++)
                    S[i][u] = fmaf(qv[i], kv[u], S[i][u]);
        }

        // Online softmax (row = 16 lanes sharing ty; xor-shfl over {8,4,2,1})
#pragma unroll
        for (int i = 0; i < 4; i++) {
            float mt = fmaxf(fmaxf(S[i][0], S[i][1]), fmaxf(S[i][2], S[i][3]));
#pragma unroll
            for (int off = 8; off >= 1; off >>= 1)
                mt = fmaxf(mt, __shfl_xor_sync(0xffffffffu, mt, off));
            float mnew  = fmaxf(m_r[i], mt);
            float alpha = __expf(m_r[i] - mnew);
            float p[4], ps = 0.f;
#pragma unroll
            for (int u = 0; u < 4; u++) { p[u] = __expf(S[i][u] - mnew); ps += p[u]; }
#pragma unroll
            for (int off = 8; off >= 1; off >>= 1)
                ps += __shfl_xor_sync(0xffffffffu, ps, off);
            l_r[i] = l_r[i] * alpha + ps;
            m_r[i] = mnew;
#pragma unroll
            for (int u = 0; u < 4; u++)
                Ps[(ty + 16 * i) * PS_LD + tx + 16 * u] = p[u];
#pragma unroll
            for (int u = 0; u < 10; u++) O[i][u] *= alpha;
        }
        __syncthreads();

        // O += P @ V  (64x160 over 64), 4 rows x 10 cols per thread
#pragma unroll 4
        for (int j = 0; j < 64; j++) {
            float pv[4], vv[10];
#pragma unroll
            for (int i = 0; i < 4; i++) pv[i] = Ps[(ty + 16 * i) * PS_LD + j];
#pragma unroll
            for (int u = 0; u < 10; u++) vv[u] = Vs[j * VS_LD + tx + 16 * u];
#pragma unroll
            for (int i = 0; i < 4; i++)
#pragma unroll
                for (int u = 0; u < 10; u++)
                    O[i][u] = fmaf(pv[i], vv[u], O[i][u]);
        }
    }

    // Epilogue: normalize, add residual, write out
    const float* xbase = gx   + ((size_t)b * SX_ + m0) * DD;
    float*       obase = gout + ((size_t)b * SX_ + m0) * DD;
#pragma unroll
    for (int i = 0; i < 4; i++) {
        float inv = 1.f / l_r[i];
        int r = ty + 16 * i;
#pragma unroll
        for (int u = 0; u < 10; u++) {
            int e = tx + 16 * u;
            obase[(size_t)r * DD + e] = O[i][u] * inv + xbase[(size_t)r * DD + e];
        }
    }
}

// ---------------------------------------------------------------------------
extern "C" void kernel_launch(void* const* d_in, const int* in_sizes, int n_in,
                              void* d_out, int out_size)
{
    const float* x  = (const float*)d_in[0];
    const float* y  = (const float*)d_in[1];
    const float* Wq = (const float*)d_in[2];
    const float* bq = (const float*)d_in[3];
    const float* Wk = (const float*)d_in[4];
    const float* bk = (const float*)d_in[5];
    const float* Wv = (const float*)d_in[6];
    const float* bv = (const float*)d_in[7];
    float* out = (float*)d_out;

    float *qp, *kp, *vp;
    cudaGetSymbolAddress((void**)&qp, g_q);
    cudaGetSymbolAddress((void**)&kp, g_k);
    cudaGetSymbolAddress((void**)&vp, g_v);

    proj_kernel<<<(B_ * SX_) / 64, 256>>>(x, Wq, bq, qp);
    proj_kernel<<<(B_ * SY_) / 64, 256>>>(y, Wk, bk, kp);
    proj_kernel<<<(B_ * SY_) / 64, 256>>>(y, Wv, bv, vp);

    const int smem_bytes = SMEM_FLOATS * (int)sizeof(float);  // 141056 B
    cudaFuncSetAttribute(attn_kernel,
                         cudaFuncAttributeMaxDynamicSharedMemorySize, smem_bytes);
    dim3 grid(SX_ / 64, B_);
    attn_kernel<<<grid, 256, smem_bytes>>>(qp, kp, vp, x, out);
}